// round 1
// baseline (speedup 1.0000x reference)
#include <cuda_runtime.h>
#include <cstdint>

#define BATCH   2
#define NSEQ    2048
#define CH      768
#define NH      12
#define DH      64
#define WIN     7
#define C3      (3*CH)

// Scratch (allocation-free contract): qkv intermediate and attention output.
__device__ float g_qkv[(size_t)BATCH * NSEQ * C3];   // [B,N,3C]  ~37.7 MB
__device__ float g_att[(size_t)BATCH * NSEQ * CH];   // [B,N,C]   ~12.6 MB

typedef unsigned long long ull;

__device__ __forceinline__ ull pk2(float x, float y) {
    ull r;
    asm("mov.b64 %0, {%1, %2};" : "=l"(r)
        : "r"(__float_as_uint(x)), "r"(__float_as_uint(y)));
    return r;
}
__device__ __forceinline__ void upk2(ull v, float& x, float& y) {
    unsigned a, b;
    asm("mov.b64 {%0, %1}, %2;" : "=r"(a), "=r"(b) : "l"(v));
    x = __uint_as_float(a); y = __uint_as_float(b);
}
// d += a * b   (packed f32x2, Blackwell FFMA2 path)
__device__ __forceinline__ void fma2(ull& d, ull a, ull b) {
    asm("fma.rn.f32x2 %0, %1, %2, %0;" : "+l"(d) : "l"(a), "l"(b));
}

// C[M,N] = A[M,K] @ W[N,K]^T (+bias[n]).  Both A and W are K-major (row-major
// with K contiguous), which matches x@w.T for row-major w — no transposes.
// BM=BN=128, BK=8, 256 threads, 8x8 per thread, inner loop in fma.rn.f32x2.
__global__ void __launch_bounds__(256)
sgemm_nt_f32x2(const float* __restrict__ A, const float* __restrict__ W,
               const float* __restrict__ bias, float* __restrict__ C,
               int M, int N, int K)
{
    constexpr int BM = 128, BN = 128, BK = 8;
    __shared__ float As[BK][BM];
    __shared__ float Ws[BK][BN];

    const int tid  = threadIdx.x;
    const int rowC = blockIdx.y * BM;
    const int colC = blockIdx.x * BN;
    const int tx   = tid & 15;     // 0..15  -> 8 cols each
    const int ty   = tid >> 4;     // 0..15  -> 8 rows each

    // global-load mapping: 128 rows x 2 float4 per row
    const int lr = tid >> 1;            // 0..127
    const int lc = (tid & 1) * 4;       // 0 or 4
    const float* Ap = A + (size_t)(rowC + lr) * K + lc;
    const float* Wp = W + (size_t)(colC + lr) * K + lc;

    ull acc[8][4];
    #pragma unroll
    for (int i = 0; i < 8; i++)
        #pragma unroll
        for (int j = 0; j < 4; j++) acc[i][j] = 0ull;

    for (int k0 = 0; k0 < K; k0 += BK) {
        float4 a = *(const float4*)(Ap + k0);
        float4 w = *(const float4*)(Wp + k0);
        As[lc + 0][lr] = a.x; As[lc + 1][lr] = a.y;
        As[lc + 2][lr] = a.z; As[lc + 3][lr] = a.w;
        Ws[lc + 0][lr] = w.x; Ws[lc + 1][lr] = w.y;
        Ws[lc + 2][lr] = w.z; Ws[lc + 3][lr] = w.w;
        __syncthreads();

        #pragma unroll
        for (int k = 0; k < BK; k++) {
            float4 a0 = *(const float4*)&As[k][ty * 8];
            float4 a1 = *(const float4*)&As[k][ty * 8 + 4];
            float4 b0 = *(const float4*)&Ws[k][tx * 8];
            float4 b1 = *(const float4*)&Ws[k][tx * 8 + 4];
            ull bb[4] = { pk2(b0.x, b0.y), pk2(b0.z, b0.w),
                          pk2(b1.x, b1.y), pk2(b1.z, b1.w) };
            float av[8] = { a0.x, a0.y, a0.z, a0.w, a1.x, a1.y, a1.z, a1.w };
            #pragma unroll
            for (int i = 0; i < 8; i++) {
                ull aa = pk2(av[i], av[i]);
                fma2(acc[i][0], aa, bb[0]);
                fma2(acc[i][1], aa, bb[1]);
                fma2(acc[i][2], aa, bb[2]);
                fma2(acc[i][3], aa, bb[3]);
            }
        }
        __syncthreads();
    }

    // epilogue
    #pragma unroll
    for (int i = 0; i < 8; i++) {
        float o[8];
        #pragma unroll
        for (int j = 0; j < 4; j++) upk2(acc[i][j], o[2*j], o[2*j + 1]);
        const int col = colC + tx * 8;
        if (bias) {
            #pragma unroll
            for (int t = 0; t < 8; t++) o[t] += bias[col + t];
        }
        const int row = rowC + ty * 8 + i;
        float4* dst = (float4*)&C[(size_t)row * N + col];
        dst[0] = make_float4(o[0], o[1], o[2], o[3]);
        dst[1] = make_float4(o[4], o[5], o[6], o[7]);
    }
}

// Local-window attention: one warp per (b, h, i). Dh=64 -> float2 per lane.
__global__ void __launch_bounds__(256)
local_attn(const float* __restrict__ qkv, float* __restrict__ out)
{
    const int wid  = (blockIdx.x * blockDim.x + threadIdx.x) >> 5;
    const int lane = threadIdx.x & 31;

    const int i = wid % NSEQ;
    const int t = wid / NSEQ;
    const int h = t % NH;
    const int b = t / NH;

    const int doff = h * DH + 2 * lane;
    const size_t rowq = ((size_t)b * NSEQ + i) * C3;
    const float2 q = *(const float2*)(qkv + rowq + doff);

    const float scale = 0.125f;  // Dh^-0.5 = 1/8
    const int j0 = (i - WIN > 0) ? i - WIN : 0;
    const int j1 = (i + WIN < NSEQ - 1) ? i + WIN : NSEQ - 1;

    float logits[2 * WIN + 1];
    for (int j = j0; j <= j1; j++) {
        const size_t rowk = ((size_t)b * NSEQ + j) * C3 + CH;
        const float2 k = *(const float2*)(qkv + rowk + doff);
        float s = q.x * k.x + q.y * k.y;
        #pragma unroll
        for (int o = 16; o; o >>= 1) s += __shfl_xor_sync(0xffffffffu, s, o);
        logits[j - j0] = s * scale;
    }

    float m = -1e30f;
    for (int j = j0; j <= j1; j++) m = fmaxf(m, logits[j - j0]);

    float den = 0.f;
    float2 acc = make_float2(0.f, 0.f);
    for (int j = j0; j <= j1; j++) {
        const float p = __expf(logits[j - j0] - m);
        den += p;
        const size_t rowv = ((size_t)b * NSEQ + j) * C3 + 2 * CH;
        const float2 v = *(const float2*)(qkv + rowv + doff);
        acc.x += p * v.x;
        acc.y += p * v.y;
    }
    const float inv = 1.f / den;
    float2 r = make_float2(acc.x * inv, acc.y * inv);
    *(float2*)(out + ((size_t)b * NSEQ + i) * CH + doff) = r;
}

extern "C" void kernel_launch(void* const* d_in, const int* in_sizes, int n_in,
                              void* d_out, int out_size)
{
    const float* x      = (const float*)d_in[0];  // [B,N,C]
    const float* w_qkv  = (const float*)d_in[1];  // [3C,C]
    const float* w_proj = (const float*)d_in[2];  // [C,C]
    const float* b_proj = (const float*)d_in[3];  // [C]
    float* out = (float*)d_out;                   // [B,N,C]

    float *qkv, *att;
    cudaGetSymbolAddress((void**)&qkv, g_qkv);
    cudaGetSymbolAddress((void**)&att, g_att);

    const int M = BATCH * NSEQ;  // 4096

    // 1) QKV projection: [4096, 2304] = x @ w_qkv^T
    {
        dim3 grid(C3 / 128, M / 128);   // 18 x 32
        sgemm_nt_f32x2<<<grid, 256>>>(x, w_qkv, nullptr, qkv, M, C3, CH);
    }
    // 2) local-window attention -> [B,N,C]
    {
        const int warps = BATCH * NH * NSEQ;   // 49152
        local_attn<<<warps / 8, 256>>>(qkv, att);
    }
    // 3) output projection: [4096, 768] = att @ w_proj^T + b
    {
        dim3 grid(CH / 128, M / 128);   // 6 x 32
        sgemm_nt_f32x2<<<grid, 256>>>(att, w_proj, b_proj, out, M, CH, CH);
    }
}

// round 3
// speedup vs baseline: 2.2159x; 2.2159x over previous
#include <cuda_runtime.h>
#include <cuda_bf16.h>
#include <cstdint>

#define BATCH 2
#define NSEQ  2048
#define CH    768
#define NH    12
#define DH    64
#define WIN   7
#define C3    (3*CH)
#define MTOT  (BATCH*NSEQ)   // 4096
#define KDIM  CH             // 768 (K for both GEMMs)

#define BM 128
#define BN 128
#define BK 32
#define NCHUNK (KDIM/BK)     // 24
#define TILEB  8192          // 128 rows x 64 B (32 bf16)
#define STAGEB (4*TILEB)     // Ahi, Alo, Whi, Wlo = 32 KB
#define SMEM_TOTAL (2*STAGEB)// 64 KB

// ---------------- scratch (allocation-free) ----------------
__device__ float         g_qkv[(size_t)MTOT*C3];
__device__ __nv_bfloat16 g_xhi[(size_t)MTOT*CH], g_xlo[(size_t)MTOT*CH];
__device__ __nv_bfloat16 g_qhi[(size_t)C3*CH],  g_qlo[(size_t)C3*CH];
__device__ __nv_bfloat16 g_phi[(size_t)CH*CH],  g_plo[(size_t)CH*CH];
__device__ __nv_bfloat16 g_ahi[(size_t)MTOT*CH], g_alo[(size_t)MTOT*CH];

// ---------------- helpers ----------------
__device__ __forceinline__ uint32_t smem_u32(const void* p) {
    uint32_t a;
    asm("{ .reg .u64 t; cvta.to.shared.u64 t, %1; cvt.u32.u64 %0, t; }" : "=r"(a) : "l"(p));
    return a;
}
__device__ __forceinline__ void cp16(uint32_t dst, const void* src) {
    asm volatile("cp.async.cg.shared.global [%0], [%1], 16;" :: "r"(dst), "l"(src) : "memory");
}
#define CP_COMMIT() asm volatile("cp.async.commit_group;" ::: "memory")
#define CP_WAIT1()  asm volatile("cp.async.wait_group 1;" ::: "memory")

#define LDSM_X4(r0, r1, r2, r3, addr)                                         \
    asm volatile("ldmatrix.sync.aligned.m8n8.x4.shared.b16 {%0,%1,%2,%3}, [%4];" \
                 : "=r"(r0), "=r"(r1), "=r"(r2), "=r"(r3) : "r"(addr))

#define MMA_BF16(acc, a, b0, b1)                                              \
    asm("mma.sync.aligned.m16n8k16.row.col.f32.bf16.bf16.f32 "                \
        "{%0,%1,%2,%3},{%4,%5,%6,%7},{%8,%9},{%0,%1,%2,%3};"                  \
        : "+f"((acc)[0]), "+f"((acc)[1]), "+f"((acc)[2]), "+f"((acc)[3])      \
        : "r"((a)[0]), "r"((a)[1]), "r"((a)[2]), "r"((a)[3]),                 \
          "r"(b0), "r"(b1))

// swizzled smem offset within a 128x64B tile: row*64 + (colb ^ ((row&6)<<3))
__device__ __forceinline__ uint32_t swz(int row, int colb) {
    return (uint32_t)(row * 64 + (colb ^ ((row & 6) << 3)));
}

// ---------------- fp32 -> bf16 hi/lo split ----------------
__global__ void __launch_bounds__(256)
split_bf16(const float* __restrict__ in, __nv_bfloat16* __restrict__ hi,
           __nv_bfloat16* __restrict__ lo, int n4)
{
    int idx = blockIdx.x * blockDim.x + threadIdx.x;
    if (idx >= n4) return;
    float4 v = ((const float4*)in)[idx];
    __nv_bfloat16 h0 = __float2bfloat16(v.x), h1 = __float2bfloat16(v.y);
    __nv_bfloat16 h2 = __float2bfloat16(v.z), h3 = __float2bfloat16(v.w);
    __nv_bfloat16 l0 = __float2bfloat16(v.x - __bfloat162float(h0));
    __nv_bfloat16 l1 = __float2bfloat16(v.y - __bfloat162float(h1));
    __nv_bfloat16 l2 = __float2bfloat16(v.z - __bfloat162float(h2));
    __nv_bfloat16 l3 = __float2bfloat16(v.w - __bfloat162float(h3));
    __nv_bfloat162* hp = (__nv_bfloat162*)(hi + 4 * (size_t)idx);
    __nv_bfloat162* lp = (__nv_bfloat162*)(lo + 4 * (size_t)idx);
    hp[0] = __nv_bfloat162(h0, h1); hp[1] = __nv_bfloat162(h2, h3);
    lp[0] = __nv_bfloat162(l0, l1); lp[1] = __nv_bfloat162(l2, l3);
}

// ---------------- fill one pipeline stage (4 tiles) via cp.async ----------------
__device__ __forceinline__ void fill_stage(uint32_t stb,
    const char* Ah, const char* Al, const char* Wh, const char* Wl,
    int m0, int n0, int k0, int tid)
{
    #pragma unroll
    for (int t = 0; t < 2; t++) {
        int seg = tid + t * 256;          // 512 16B segments per tile
        int row = seg >> 2, ks = seg & 3; // 4 segments per 64B row
        uint32_t so = swz(row, ks * 16);
        size_t ga = ((size_t)(m0 + row) * KDIM + k0 + ks * 8) * 2;
        size_t gw = ((size_t)(n0 + row) * KDIM + k0 + ks * 8) * 2;
        cp16(stb + so,             Ah + ga);
        cp16(stb + TILEB + so,     Al + ga);
        cp16(stb + 2 * TILEB + so, Wh + gw);
        cp16(stb + 3 * TILEB + so, Wl + gw);
    }
}

// ---------------- HMMA GEMM: C[M,N] = A@W^T (+bias), 3x bf16-split ----------------
__global__ void __launch_bounds__(256)
gemm_mma(const __nv_bfloat16* __restrict__ Ahi, const __nv_bfloat16* __restrict__ Alo,
         const __nv_bfloat16* __restrict__ Whi, const __nv_bfloat16* __restrict__ Wlo,
         const float* __restrict__ bias, float* __restrict__ C, int N)
{
    extern __shared__ char smem[];
    const uint32_t sb = smem_u32(smem);
    const int tid = threadIdx.x, wid = tid >> 5, lane = tid & 31;
    const int m0 = blockIdx.y * BM, n0 = blockIdx.x * BN;
    const int wm = (wid & 3) * 32;     // warp m offset (4 warps over 128)
    const int wn = (wid >> 2) * 64;    // warp n offset (2 warps over 128)

    const char* pAh = (const char*)Ahi;
    const char* pAl = (const char*)Alo;
    const char* pWh = (const char*)Whi;
    const char* pWl = (const char*)Wlo;

    float acc[2][8][4];
    #pragma unroll
    for (int i = 0; i < 2; i++)
        #pragma unroll
        for (int j = 0; j < 8; j++)
            #pragma unroll
            for (int t = 0; t < 4; t++) acc[i][j][t] = 0.f;

    // prologue: stages 0,1 <- chunks 0,1
    fill_stage(sb,          pAh, pAl, pWh, pWl, m0, n0, 0,  tid); CP_COMMIT();
    fill_stage(sb + STAGEB, pAh, pAl, pWh, pWl, m0, n0, BK, tid); CP_COMMIT();

    const int r  = lane & 15, cg = lane >> 4;

    for (int c = 0; c < NCHUNK; c++) {
        const uint32_t stb = sb + (c & 1) * STAGEB;
        CP_WAIT1();
        __syncthreads();

        uint32_t ah[2][4], al[2][4], bh[4][4], bl[4][4];

        // ---- k-step 0 ----
        #pragma unroll
        for (int mt = 0; mt < 2; mt++) {
            int row = wm + mt * 16 + r;
            uint32_t ad = stb + swz(row, cg * 16);
            LDSM_X4(ah[mt][0], ah[mt][1], ah[mt][2], ah[mt][3], ad);
            LDSM_X4(al[mt][0], al[mt][1], al[mt][2], al[mt][3], ad + TILEB);
        }
        #pragma unroll
        for (int bt = 0; bt < 4; bt++) {
            int row = wn + bt * 16 + r;
            uint32_t ad = stb + 2 * TILEB + swz(row, cg * 16);
            LDSM_X4(bh[bt][0], bh[bt][1], bh[bt][2], bh[bt][3], ad);
            LDSM_X4(bl[bt][0], bl[bt][1], bl[bt][2], bl[bt][3], ad + TILEB);
        }
        #pragma unroll
        for (int mt = 0; mt < 2; mt++)
            #pragma unroll
            for (int nt = 0; nt < 8; nt++) {
                uint32_t b0h = bh[nt >> 1][nt & 1], b1h = bh[nt >> 1][2 + (nt & 1)];
                uint32_t b0l = bl[nt >> 1][nt & 1], b1l = bl[nt >> 1][2 + (nt & 1)];
                MMA_BF16(acc[mt][nt], ah[mt], b0h, b1h);
                MMA_BF16(acc[mt][nt], ah[mt], b0l, b1l);
                MMA_BF16(acc[mt][nt], al[mt], b0h, b1h);
            }

        // ---- k-step 1: load frags, then release stage & refill ----
        #pragma unroll
        for (int mt = 0; mt < 2; mt++) {
            int row = wm + mt * 16 + r;
            uint32_t ad = stb + swz(row, 32 + cg * 16);
            LDSM_X4(ah[mt][0], ah[mt][1], ah[mt][2], ah[mt][3], ad);
            LDSM_X4(al[mt][0], al[mt][1], al[mt][2], al[mt][3], ad + TILEB);
        }
        #pragma unroll
        for (int bt = 0; bt < 4; bt++) {
            int row = wn + bt * 16 + r;
            uint32_t ad = stb + 2 * TILEB + swz(row, 32 + cg * 16);
            LDSM_X4(bh[bt][0], bh[bt][1], bh[bt][2], bh[bt][3], ad);
            LDSM_X4(bl[bt][0], bl[bt][1], bl[bt][2], bl[bt][3], ad + TILEB);
        }
        __syncthreads();   // everyone done reading this stage
        if (c + 2 < NCHUNK)
            fill_stage(stb, pAh, pAl, pWh, pWl, m0, n0, (c + 2) * BK, tid);
        CP_COMMIT();       // unconditional: empty groups keep wait-count bookkeeping simple

        #pragma unroll
        for (int mt = 0; mt < 2; mt++)
            #pragma unroll
            for (int nt = 0; nt < 8; nt++) {
                uint32_t b0h = bh[nt >> 1][nt & 1], b1h = bh[nt >> 1][2 + (nt & 1)];
                uint32_t b0l = bl[nt >> 1][nt & 1], b1l = bl[nt >> 1][2 + (nt & 1)];
                MMA_BF16(acc[mt][nt], ah[mt], b0h, b1h);
                MMA_BF16(acc[mt][nt], ah[mt], b0l, b1l);
                MMA_BF16(acc[mt][nt], al[mt], b0h, b1h);
            }
    }

    // ---- epilogue ----
    const int g = lane >> 2, tg = lane & 3;
    #pragma unroll
    for (int mt = 0; mt < 2; mt++)
        #pragma unroll
        for (int nt = 0; nt < 8; nt++) {
            int row = m0 + wm + mt * 16 + g;
            int col = n0 + wn + nt * 8 + tg * 2;
            float b0v = 0.f, b1v = 0.f;
            if (bias) { b0v = __ldg(&bias[col]); b1v = __ldg(&bias[col + 1]); }
            float2* d0 = (float2*)&C[(size_t)row * N + col];
            float2* d1 = (float2*)&C[(size_t)(row + 8) * N + col];
            *d0 = make_float2(acc[mt][nt][0] + b0v, acc[mt][nt][1] + b1v);
            *d1 = make_float2(acc[mt][nt][2] + b0v, acc[mt][nt][3] + b1v);
        }
}

// ---------------- local-window attention; writes bf16 hi/lo directly ----------------
__global__ void __launch_bounds__(256)
local_attn(const float* __restrict__ qkv, __nv_bfloat16* __restrict__ ohi,
           __nv_bfloat16* __restrict__ olo)
{
    const int wid  = (blockIdx.x * blockDim.x + threadIdx.x) >> 5;
    const int lane = threadIdx.x & 31;

    const int i = wid % NSEQ;
    const int t = wid / NSEQ;
    const int h = t % NH;
    const int b = t / NH;

    const int doff = h * DH + 2 * lane;
    const size_t rbase = (size_t)b * NSEQ;
    const float2 q = *(const float2*)(qkv + (rbase + i) * C3 + doff);
    const float scale = 0.125f;

    float2 acc = make_float2(0.f, 0.f);
    float den;

    if (i >= WIN && i < NSEQ - WIN) {
        float lg[2 * WIN + 1];
        #pragma unroll
        for (int jj = 0; jj < 2 * WIN + 1; jj++) {
            const float2 k = *(const float2*)(qkv + (rbase + i - WIN + jj) * C3 + CH + doff);
            float s = q.x * k.x + q.y * k.y;
            #pragma unroll
            for (int o = 16; o; o >>= 1) s += __shfl_xor_sync(0xffffffffu, s, o);
            lg[jj] = s * scale;
        }
        float m = lg[0];
        #pragma unroll
        for (int jj = 1; jj < 2 * WIN + 1; jj++) m = fmaxf(m, lg[jj]);
        den = 0.f;
        #pragma unroll
        for (int jj = 0; jj < 2 * WIN + 1; jj++) {
            const float p = __expf(lg[jj] - m);
            den += p;
            const float2 v = *(const float2*)(qkv + (rbase + i - WIN + jj) * C3 + 2 * CH + doff);
            acc.x += p * v.x; acc.y += p * v.y;
        }
    } else {
        const int j0 = (i - WIN > 0) ? i - WIN : 0;
        const int j1 = (i + WIN < NSEQ - 1) ? i + WIN : NSEQ - 1;
        float lg[2 * WIN + 1];
        for (int j = j0; j <= j1; j++) {
            const float2 k = *(const float2*)(qkv + (rbase + j) * C3 + CH + doff);
            float s = q.x * k.x + q.y * k.y;
            #pragma unroll
            for (int o = 16; o; o >>= 1) s += __shfl_xor_sync(0xffffffffu, s, o);
            lg[j - j0] = s * scale;
        }
        float m = -1e30f;
        for (int j = j0; j <= j1; j++) m = fmaxf(m, lg[j - j0]);
        den = 0.f;
        for (int j = j0; j <= j1; j++) {
            const float p = __expf(lg[j - j0] - m);
            den += p;
            const float2 v = *(const float2*)(qkv + (rbase + j) * C3 + 2 * CH + doff);
            acc.x += p * v.x; acc.y += p * v.y;
        }
    }
    const float inv = 1.f / den;
    const float rx = acc.x * inv, ry = acc.y * inv;
    const __nv_bfloat16 hx = __float2bfloat16(rx), hy = __float2bfloat16(ry);
    const __nv_bfloat16 lx = __float2bfloat16(rx - __bfloat162float(hx));
    const __nv_bfloat16 ly = __float2bfloat16(ry - __bfloat162float(hy));
    const size_t off = (rbase + i) * CH + doff;
    *(__nv_bfloat162*)(ohi + off) = __nv_bfloat162(hx, hy);
    *(__nv_bfloat162*)(olo + off) = __nv_bfloat162(lx, ly);
}

// ---------------- launch ----------------
extern "C" void kernel_launch(void* const* d_in, const int* in_sizes, int n_in,
                              void* d_out, int out_size)
{
    const float* x      = (const float*)d_in[0];
    const float* w_qkv  = (const float*)d_in[1];
    const float* w_proj = (const float*)d_in[2];
    const float* b_proj = (const float*)d_in[3];
    float* out = (float*)d_out;

    float* qkv;
    __nv_bfloat16 *xhi, *xlo, *qhi, *qlo, *phi, *plo, *ahi, *alo;
    cudaGetSymbolAddress((void**)&qkv, g_qkv);
    cudaGetSymbolAddress((void**)&xhi, g_xhi); cudaGetSymbolAddress((void**)&xlo, g_xlo);
    cudaGetSymbolAddress((void**)&qhi, g_qhi); cudaGetSymbolAddress((void**)&qlo, g_qlo);
    cudaGetSymbolAddress((void**)&phi, g_phi); cudaGetSymbolAddress((void**)&plo, g_plo);
    cudaGetSymbolAddress((void**)&ahi, g_ahi); cudaGetSymbolAddress((void**)&alo, g_alo);

    cudaFuncSetAttribute(gemm_mma, cudaFuncAttributeMaxDynamicSharedMemorySize, SMEM_TOTAL);

    // 1) splits
    {
        int n4 = MTOT * CH / 4;
        split_bf16<<<(n4 + 255) / 256, 256>>>(x, xhi, xlo, n4);
        n4 = C3 * CH / 4;
        split_bf16<<<(n4 + 255) / 256, 256>>>(w_qkv, qhi, qlo, n4);
        n4 = CH * CH / 4;
        split_bf16<<<(n4 + 255) / 256, 256>>>(w_proj, phi, plo, n4);
    }
    // 2) QKV GEMM: [4096, 2304]
    {
        dim3 grid(C3 / BN, MTOT / BM);   // 18 x 32
        gemm_mma<<<grid, 256, SMEM_TOTAL>>>(xhi, xlo, qhi, qlo, nullptr, qkv, C3);
    }
    // 3) attention -> bf16 hi/lo
    {
        const int warps = BATCH * NH * NSEQ;
        local_attn<<<warps / 8, 256>>>(qkv, ahi, alo);
    }
    // 4) proj GEMM: [4096, 768] + bias
    {
        dim3 grid(CH / BN, MTOT / BM);   // 6 x 32
        gemm_mma<<<grid, 256, SMEM_TOTAL>>>(ahi, alo, phi, plo, b_proj, out, CH);
    }
}

// round 4
// speedup vs baseline: 2.2682x; 1.0236x over previous
#include <cuda_runtime.h>
#include <cuda_bf16.h>
#include <cstdint>

#define BATCH 2
#define NSEQ  2048
#define CH    768
#define NH    12
#define DH    64
#define WIN   7
#define C3    (3*CH)
#define MTOT  (BATCH*NSEQ)   // 4096
#define KDIM  CH             // 768
#define BK    32
#define NCHUNK (KDIM/BK)     // 24
#define NSTAGE 3

// ---------------- scratch (allocation-free) ----------------
__device__ float         g_qkv[(size_t)MTOT*C3];
__device__ __nv_bfloat16 g_xhi[(size_t)MTOT*CH], g_xlo[(size_t)MTOT*CH];
__device__ __nv_bfloat16 g_qhi[(size_t)C3*CH],  g_qlo[(size_t)C3*CH];
__device__ __nv_bfloat16 g_phi[(size_t)CH*CH],  g_plo[(size_t)CH*CH];
__device__ __nv_bfloat16 g_ahi[(size_t)MTOT*CH], g_alo[(size_t)MTOT*CH];

// ---------------- helpers ----------------
__device__ __forceinline__ uint32_t smem_u32(const void* p) {
    uint32_t a;
    asm("{ .reg .u64 t; cvta.to.shared.u64 t, %1; cvt.u32.u64 %0, t; }" : "=r"(a) : "l"(p));
    return a;
}
__device__ __forceinline__ void cp16(uint32_t dst, const void* src) {
    asm volatile("cp.async.cg.shared.global [%0], [%1], 16;" :: "r"(dst), "l"(src) : "memory");
}
#define CP_COMMIT() asm volatile("cp.async.commit_group;" ::: "memory")
#define CP_WAIT2()  asm volatile("cp.async.wait_group 2;" ::: "memory")

#define LDSM_X4(r0, r1, r2, r3, addr)                                            \
    asm volatile("ldmatrix.sync.aligned.m8n8.x4.shared.b16 {%0,%1,%2,%3}, [%4];" \
                 : "=r"(r0), "=r"(r1), "=r"(r2), "=r"(r3) : "r"(addr))

#define MMA_BF16(acc, a, b0, b1)                                              \
    asm("mma.sync.aligned.m16n8k16.row.col.f32.bf16.bf16.f32 "                \
        "{%0,%1,%2,%3},{%4,%5,%6,%7},{%8,%9},{%0,%1,%2,%3};"                  \
        : "+f"((acc)[0]), "+f"((acc)[1]), "+f"((acc)[2]), "+f"((acc)[3])      \
        : "r"((a)[0]), "r"((a)[1]), "r"((a)[2]), "r"((a)[3]),                 \
          "r"(b0), "r"(b1))

// swizzled offset within a rows x 64B tile
__device__ __forceinline__ uint32_t swz(int row, int colb) {
    return (uint32_t)(row * 64 + (colb ^ ((row & 6) << 3)));
}

// ---------------- fp32 -> bf16 hi/lo split ----------------
__global__ void __launch_bounds__(256)
split_bf16(const float* __restrict__ in, __nv_bfloat16* __restrict__ hi,
           __nv_bfloat16* __restrict__ lo, int n4)
{
    int idx = blockIdx.x * blockDim.x + threadIdx.x;
    if (idx >= n4) return;
    float4 v = ((const float4*)in)[idx];
    __nv_bfloat16 h0 = __float2bfloat16(v.x), h1 = __float2bfloat16(v.y);
    __nv_bfloat16 h2 = __float2bfloat16(v.z), h3 = __float2bfloat16(v.w);
    __nv_bfloat16 l0 = __float2bfloat16(v.x - __bfloat162float(h0));
    __nv_bfloat16 l1 = __float2bfloat16(v.y - __bfloat162float(h1));
    __nv_bfloat16 l2 = __float2bfloat16(v.z - __bfloat162float(h2));
    __nv_bfloat16 l3 = __float2bfloat16(v.w - __bfloat162float(h3));
    __nv_bfloat162* hp = (__nv_bfloat162*)(hi + 4 * (size_t)idx);
    __nv_bfloat162* lp = (__nv_bfloat162*)(lo + 4 * (size_t)idx);
    hp[0] = __nv_bfloat162(h0, h1); hp[1] = __nv_bfloat162(h2, h3);
    lp[0] = __nv_bfloat162(l0, l1); lp[1] = __nv_bfloat162(l2, l3);
}

// ---------------- HMMA GEMM, templated on BM / threads ----------------
// Stage layout: [Ahi BM*64][Alo BM*64][Whi 8192][Wlo 8192]
template<int BM_, int NT>
__global__ void __launch_bounds__(NT, 1)
gemm_mma(const __nv_bfloat16* __restrict__ Ahi, const __nv_bfloat16* __restrict__ Alo,
         const __nv_bfloat16* __restrict__ Whi, const __nv_bfloat16* __restrict__ Wlo,
         const float* __restrict__ bias, float* __restrict__ C, int N)
{
    constexpr int WARPS_M = BM_ / 32;
    constexpr int ATILE   = BM_ * 64;
    constexpr int STAGEB  = 2 * ATILE + 16384;

    extern __shared__ char smem[];
    const uint32_t sb = smem_u32(smem);
    const int tid = threadIdx.x, wid = tid >> 5, lane = tid & 31;
    const int m0 = blockIdx.y * BM_, n0 = blockIdx.x * 128;
    const int wm = (wid % WARPS_M) * 32;
    const int wn = (wid / WARPS_M) * 32;

    const char* pAh = (const char*)Ahi;
    const char* pAl = (const char*)Alo;
    const char* pWh = (const char*)Whi;
    const char* pWl = (const char*)Wlo;

    float acc[2][4][4];
    #pragma unroll
    for (int i = 0; i < 2; i++)
        #pragma unroll
        for (int j = 0; j < 4; j++)
            #pragma unroll
            for (int t = 0; t < 4; t++) acc[i][j][t] = 0.f;

    auto fill_stage = [&](uint32_t stb, int k0) {
        #pragma unroll
        for (int s = tid; s < BM_ * 4; s += NT) {
            int row = s >> 2, ks = s & 3;
            uint32_t so = swz(row, ks * 16);
            size_t ga = ((size_t)(m0 + row) * KDIM + k0 + ks * 8) * 2;
            cp16(stb + so,         pAh + ga);
            cp16(stb + ATILE + so, pAl + ga);
        }
        #pragma unroll
        for (int s = tid; s < 512; s += NT) {
            int row = s >> 2, ks = s & 3;
            uint32_t so = swz(row, ks * 16);
            size_t gw = ((size_t)(n0 + row) * KDIM + k0 + ks * 8) * 2;
            cp16(stb + 2 * ATILE + so,        pWh + gw);
            cp16(stb + 2 * ATILE + 8192 + so, pWl + gw);
        }
    };

    // prologue: 3 stages
    #pragma unroll
    for (int c = 0; c < NSTAGE; c++) {
        fill_stage(sb + c * STAGEB, c * BK);
        CP_COMMIT();
    }

    const int r = lane & 15, cg = lane >> 4;

    for (int c = 0; c < NCHUNK; c++) {
        const uint32_t stb = sb + (c % NSTAGE) * STAGEB;
        CP_WAIT2();
        __syncthreads();

        uint32_t ah[2][4], al[2][4], bh[2][4], bl[2][4];

        // ---- k-step 0 ----
        #pragma unroll
        for (int mt = 0; mt < 2; mt++) {
            uint32_t ad = stb + swz(wm + mt * 16 + r, cg * 16);
            LDSM_X4(ah[mt][0], ah[mt][1], ah[mt][2], ah[mt][3], ad);
            LDSM_X4(al[mt][0], al[mt][1], al[mt][2], al[mt][3], ad + ATILE);
        }
        #pragma unroll
        for (int bt = 0; bt < 2; bt++) {
            uint32_t ad = stb + 2 * ATILE + swz(wn + bt * 16 + r, cg * 16);
            LDSM_X4(bh[bt][0], bh[bt][1], bh[bt][2], bh[bt][3], ad);
            LDSM_X4(bl[bt][0], bl[bt][1], bl[bt][2], bl[bt][3], ad + 8192);
        }
        #pragma unroll
        for (int mt = 0; mt < 2; mt++)
            #pragma unroll
            for (int nt = 0; nt < 4; nt++) {
                uint32_t b0h = bh[nt >> 1][nt & 1], b1h = bh[nt >> 1][2 + (nt & 1)];
                uint32_t b0l = bl[nt >> 1][nt & 1], b1l = bl[nt >> 1][2 + (nt & 1)];
                MMA_BF16(acc[mt][nt], ah[mt], b0h, b1h);
                MMA_BF16(acc[mt][nt], ah[mt], b0l, b1l);
                MMA_BF16(acc[mt][nt], al[mt], b0h, b1h);
            }

        // ---- k-step 1: load frags, release stage, refill, compute ----
        #pragma unroll
        for (int mt = 0; mt < 2; mt++) {
            uint32_t ad = stb + swz(wm + mt * 16 + r, 32 + cg * 16);
            LDSM_X4(ah[mt][0], ah[mt][1], ah[mt][2], ah[mt][3], ad);
            LDSM_X4(al[mt][0], al[mt][1], al[mt][2], al[mt][3], ad + ATILE);
        }
        #pragma unroll
        for (int bt = 0; bt < 2; bt++) {
            uint32_t ad = stb + 2 * ATILE + swz(wn + bt * 16 + r, 32 + cg * 16);
            LDSM_X4(bh[bt][0], bh[bt][1], bh[bt][2], bh[bt][3], ad);
            LDSM_X4(bl[bt][0], bl[bt][1], bl[bt][2], bl[bt][3], ad + 8192);
        }
        __syncthreads();
        if (c + NSTAGE < NCHUNK)
            fill_stage(stb, (c + NSTAGE) * BK);
        CP_COMMIT();

        #pragma unroll
        for (int mt = 0; mt < 2; mt++)
            #pragma unroll
            for (int nt = 0; nt < 4; nt++) {
                uint32_t b0h = bh[nt >> 1][nt & 1], b1h = bh[nt >> 1][2 + (nt & 1)];
                uint32_t b0l = bl[nt >> 1][nt & 1], b1l = bl[nt >> 1][2 + (nt & 1)];
                MMA_BF16(acc[mt][nt], ah[mt], b0h, b1h);
                MMA_BF16(acc[mt][nt], ah[mt], b0l, b1l);
                MMA_BF16(acc[mt][nt], al[mt], b0h, b1h);
            }
    }

    // ---- epilogue ----
    const int g = lane >> 2, tg = lane & 3;
    #pragma unroll
    for (int mt = 0; mt < 2; mt++)
        #pragma unroll
        for (int nt = 0; nt < 4; nt++) {
            int row = m0 + wm + mt * 16 + g;
            int col = n0 + wn + nt * 8 + tg * 2;
            float b0v = 0.f, b1v = 0.f;
            if (bias) { b0v = __ldg(&bias[col]); b1v = __ldg(&bias[col + 1]); }
            float2* d0 = (float2*)&C[(size_t)row * N + col];
            float2* d1 = (float2*)&C[(size_t)(row + 8) * N + col];
            *d0 = make_float2(acc[mt][nt][0] + b0v, acc[mt][nt][1] + b1v);
            *d1 = make_float2(acc[mt][nt][2] + b0v, acc[mt][nt][3] + b1v);
        }
}

// ---------------- local-window attention, smem-tiled ----------------
// One CTA per (b, h, 64-query block). k/v window staged in shared.
#define QBLK 64
#define JMAX (QBLK + 2*WIN)   // 78

__global__ void __launch_bounds__(256)
local_attn(const float* __restrict__ qkv, __nv_bfloat16* __restrict__ ohi,
           __nv_bfloat16* __restrict__ olo)
{
    __shared__ float ks[JMAX][DH];
    __shared__ float vs[JMAX][DH];

    const int blk = blockIdx.x;            // b*NH*(NSEQ/QBLK) decomposition
    const int nblk = NSEQ / QBLK;          // 32
    const int i0 = (blk % nblk) * QBLK;
    const int h  = (blk / nblk) % NH;
    const int b  = blk / (nblk * NH);

    const int tid = threadIdx.x, wid = tid >> 5, lane = tid & 31;
    const int doff = h * DH;
    const size_t rbase = (size_t)b * NSEQ;

    const int jbase = (i0 - WIN > 0) ? i0 - WIN : 0;
    const int jend  = (i0 + QBLK - 1 + WIN < NSEQ - 1) ? i0 + QBLK - 1 + WIN : NSEQ - 1;
    const int jtot  = jend - jbase + 1;

    // stage k/v rows (float2 per thread-slot)
    for (int s = tid; s < jtot * 32; s += 256) {
        const int row = s >> 5, c2 = (s & 31) * 2;
        const size_t g = (rbase + jbase + row) * C3 + doff + c2;
        *(float2*)&ks[row][c2] = *(const float2*)(qkv + g + CH);
        *(float2*)&vs[row][c2] = *(const float2*)(qkv + g + 2 * CH);
    }
    __syncthreads();

    const float scale = 0.125f;
    // 8 queries per warp
    #pragma unroll
    for (int qq = 0; qq < 8; qq++) {
        const int i = i0 + wid * 8 + qq;
        const float2 q = *(const float2*)(qkv + (rbase + i) * C3 + doff + 2 * lane);
        const int j0 = (i - WIN > 0) ? i - WIN : 0;
        const int j1 = (i + WIN < NSEQ - 1) ? i + WIN : NSEQ - 1;
        const int nj = j1 - j0 + 1;
        const int rb = j0 - jbase;

        float lg[2 * WIN + 1];
        for (int jj = 0; jj < nj; jj++) {
            const float2 k = *(const float2*)&ks[rb + jj][2 * lane];
            float s = q.x * k.x + q.y * k.y;
            #pragma unroll
            for (int o = 16; o; o >>= 1) s += __shfl_xor_sync(0xffffffffu, s, o);
            lg[jj] = s * scale;
        }
        float m = -1e30f;
        for (int jj = 0; jj < nj; jj++) m = fmaxf(m, lg[jj]);
        float den = 0.f;
        float2 acc = make_float2(0.f, 0.f);
        for (int jj = 0; jj < nj; jj++) {
            const float p = __expf(lg[jj] - m);
            den += p;
            const float2 v = *(const float2*)&vs[rb + jj][2 * lane];
            acc.x += p * v.x; acc.y += p * v.y;
        }
        const float inv = 1.f / den;
        const float rx = acc.x * inv, ry = acc.y * inv;
        const __nv_bfloat16 hx = __float2bfloat16(rx), hy = __float2bfloat16(ry);
        const __nv_bfloat16 lx = __float2bfloat16(rx - __bfloat162float(hx));
        const __nv_bfloat16 ly = __float2bfloat16(ry - __bfloat162float(hy));
        const size_t off = (rbase + i) * CH + doff + 2 * lane;
        *(__nv_bfloat162*)(ohi + off) = __nv_bfloat162(hx, hy);
        *(__nv_bfloat162*)(olo + off) = __nv_bfloat162(lx, ly);
    }
}

// ---------------- launch ----------------
extern "C" void kernel_launch(void* const* d_in, const int* in_sizes, int n_in,
                              void* d_out, int out_size)
{
    const float* x      = (const float*)d_in[0];
    const float* w_qkv  = (const float*)d_in[1];
    const float* w_proj = (const float*)d_in[2];
    const float* b_proj = (const float*)d_in[3];
    float* out = (float*)d_out;

    float* qkv;
    __nv_bfloat16 *xhi, *xlo, *qhi, *qlo, *phi, *plo, *ahi, *alo;
    cudaGetSymbolAddress((void**)&qkv, g_qkv);
    cudaGetSymbolAddress((void**)&xhi, g_xhi); cudaGetSymbolAddress((void**)&xlo, g_xlo);
    cudaGetSymbolAddress((void**)&qhi, g_qhi); cudaGetSymbolAddress((void**)&qlo, g_qlo);
    cudaGetSymbolAddress((void**)&phi, g_phi); cudaGetSymbolAddress((void**)&plo, g_plo);
    cudaGetSymbolAddress((void**)&ahi, g_ahi); cudaGetSymbolAddress((void**)&alo, g_alo);

    constexpr int SMEM_BIG   = NSTAGE * (2 * 128 * 64 + 16384);  // 96 KB
    constexpr int SMEM_SMALL = NSTAGE * (2 * 64 * 64 + 16384);   // 72 KB
    cudaFuncSetAttribute(gemm_mma<128, 512>, cudaFuncAttributeMaxDynamicSharedMemorySize, SMEM_BIG);
    cudaFuncSetAttribute(gemm_mma<64, 256>,  cudaFuncAttributeMaxDynamicSharedMemorySize, SMEM_SMALL);

    // 1) splits
    {
        int n4 = MTOT * CH / 4;
        split_bf16<<<(n4 + 255) / 256, 256>>>(x, xhi, xlo, n4);
        n4 = C3 * CH / 4;
        split_bf16<<<(n4 + 255) / 256, 256>>>(w_qkv, qhi, qlo, n4);
        n4 = CH * CH / 4;
        split_bf16<<<(n4 + 255) / 256, 256>>>(w_proj, phi, plo, n4);
    }
    // 2) QKV GEMM: [4096, 2304] = x @ w_qkv^T
    {
        dim3 grid(C3 / 128, MTOT / 128);   // 18 x 32
        gemm_mma<128, 512><<<grid, 512, SMEM_BIG>>>(xhi, xlo, qhi, qlo, nullptr, qkv, C3);
    }
    // 3) attention -> bf16 hi/lo
    {
        const int blocks = BATCH * NH * (NSEQ / QBLK);  // 768
        local_attn<<<blocks, 256>>>(qkv, ahi, alo);
    }
    // 4) proj GEMM: [4096, 768] + bias (BM=64 for wave balance)
    {
        dim3 grid(CH / 128, MTOT / 64);    // 6 x 64
        gemm_mma<64, 256><<<grid, 256, SMEM_SMALL>>>(ahi, alo, phi, plo, b_proj, out, CH);
    }
}